// round 7
// baseline (speedup 1.0000x reference)
#include <cuda_runtime.h>
#include <cuda_fp16.h>
#include <stdint.h>

// HybridMixSTEDecoder: 5 disjoint-group GEMMs (27648x512 @ 512xN_i) + bias,
// scattered into out[b, tp*9+p, joint, c]. Groups disjoint -> count/div identity.
//
// Single-pass fp16 mma.sync (A, B RN-rounded to fp16, fp32 accum; rel_err ~3e-4).
// A fragments loaded direct from gmem with full-chunk staggered register
// double-buffering (deep MLP); B double-buffered in smem via cp.async.
// Grid is (variant, m-block) so CTAs sharing token rows are schedule-adjacent
// (L2 reuse for the group-2 double read + output write combining).

// Padded group rows: g0..g4 = 88,88,144,88,88 -> 496 rows of 512 fp16.
static __device__ __align__(16) __half g_Bh[496 * 512];

// ---------------- helpers ----------------
static __device__ __forceinline__ uint32_t s2u(const void* p) {
    uint32_t a;
    asm("{ .reg .u64 t; cvta.to.shared.u64 t, %1; cvt.u32.u64 %0, t; }"
        : "=r"(a) : "l"(p));
    return a;
}
static __device__ __forceinline__ uint32_t f16x2_rn(float lo, float hi) {
    uint32_t r; asm("cvt.rn.f16x2.f32 %0, %1, %2;" : "=r"(r) : "f"(hi), "f"(lo));
    return r;  // low half = lo, high half = hi
}
static __device__ __forceinline__ void ldsm_x4(uint32_t* r, uint32_t addr) {
    asm volatile("ldmatrix.sync.aligned.m8n8.x4.shared.b16 {%0,%1,%2,%3}, [%4];"
        : "=r"(r[0]), "=r"(r[1]), "=r"(r[2]), "=r"(r[3]) : "r"(addr));
}
static __device__ __forceinline__ void ldsm_x2(uint32_t* r, uint32_t addr) {
    asm volatile("ldmatrix.sync.aligned.m8n8.x2.shared.b16 {%0,%1}, [%2];"
        : "=r"(r[0]), "=r"(r[1]) : "r"(addr));
}
static __device__ __forceinline__ void mma_f16(float* d, const uint32_t* a,
                                               const uint32_t* b) {
    asm volatile(
        "mma.sync.aligned.m16n8k16.row.col.f32.f16.f16.f32 "
        "{%0,%1,%2,%3}, {%4,%5,%6,%7}, {%8,%9}, {%0,%1,%2,%3};"
        : "+f"(d[0]), "+f"(d[1]), "+f"(d[2]), "+f"(d[3])
        : "r"(a[0]), "r"(a[1]), "r"(a[2]), "r"(a[3]), "r"(b[0]), "r"(b[1]));
}
static __device__ __forceinline__ void cp16(uint32_t dst, const void* src, int pred) {
    asm volatile(
        "{\n\t.reg .pred p;\n\tsetp.ne.b32 p, %0, 0;\n\t"
        "@p cp.async.cg.shared.global [%1], [%2], 16;\n\t}"
        :: "r"(pred), "r"(dst), "l"(src));
}

// ---------------- prep: W (f32) -> fp16 (RN), [n][512] K-major linear -------
__global__ void __launch_bounds__(256) prep_B(
    const float* __restrict__ W0, const float* __restrict__ W1,
    const float* __restrict__ W2, const float* __restrict__ W3,
    const float* __restrict__ W4)
{
    int idx = blockIdx.x * 256 + threadIdx.x;   // one thread per (grow, k4)
    if (idx >= 496 * 128) return;
    int grow = idx >> 7;
    int k = (idx & 127) << 2;
    int g, n;
    if      (grow <  88) { g = 0; n = grow;       }
    else if (grow < 176) { g = 1; n = grow -  88; }
    else if (grow < 320) { g = 2; n = grow - 176; }
    else if (grow < 408) { g = 3; n = grow - 320; }
    else                 { g = 4; n = grow - 408; }
    const float* Wg = (g == 0) ? W0 : (g == 1) ? W1 : (g == 2) ? W2
                    : (g == 3) ? W3 : W4;
    int Ng = (g == 2) ? 135 : 81;

    float4 v = make_float4(0.f, 0.f, 0.f, 0.f);
    if (n < Ng) v = *(const float4*)(Wg + n * 512 + k);

    uint32_t h01 = f16x2_rn(v.x, v.y);
    uint32_t h23 = f16x2_rn(v.z, v.w);
    *(uint2*)&g_Bh[grow * 512 + k] = make_uint2(h01, h23);
}

// ---------------- fused core ----------------
// Smem: two B stages of NPAD*128 bytes. 128B rows, XOR swizzle on 16B units.
template<int NPAD, int GS, int CO>
static __device__ __forceinline__ void decode_core(
    const float* __restrict__ tokens,
    const __half* __restrict__ BhT,
    const float* __restrict__ bias,
    float* __restrict__ out,
    int gidx, int jb3)
{
    constexpr int NT    = NPAD / 8;
    constexpr int PAIRS = NT / 2;
    constexpr int ODD   = NT & 1;
    constexpr int NREAL = (GS == 5) ? 135 : 81;
    constexpr int BB    = NPAD * 128;          // B tile bytes (one stage)
    constexpr int NB8   = NPAD * 8;            // cp.async 16B ops
    constexpr int CPIT  = (NB8 + 255) / 256;

    extern __shared__ char smem[];
    const uint32_t su = s2u(smem);

    const int tid  = threadIdx.x;
    const int wid  = tid >> 5;
    const int lane = tid & 31;

    const int m0 = blockIdx.y * 128;

    // A direct-load geometry (mma.sync m16n8k16 A-fragment layout):
    //   f0 <- (r, c), f1 <- (r+8, c), f2 <- (r, c+8), f3 <- (r+8, c+8)
    //   r = lane>>2 (within warp's 16-row slab), c = (lane&3)*2 (within k16)
    const float* aw = tokens
        + (size_t)(m0 + 16 * wid + (lane >> 2)) * 2560
        + gidx * 512 + (lane & 3) * 2;

    // ldmatrix B geometry
    const int rBo = (lane & 7) + ((lane & 16) ? 8 : 0);
    const int kuB = (lane >> 3) & 1;
    const int sw  = lane & 7;

    float acc[NT][4];
    #pragma unroll
    for (int t = 0; t < NT; t++)
        #pragma unroll
        for (int q = 0; q < 4; q++) acc[t][q] = 0.f;

    // Register double-buffer: buf[stage][j][frag]
    float2 buf[2][4][4];

    // ---- prologue: A chunk 0 fully into buf[0]; B(0) cp.async ----
    #pragma unroll
    for (int j = 0; j < 4; j++) {
        const float* ap = aw + j * 16;
        buf[0][j][0] = *(const float2*)(ap);
        buf[0][j][1] = *(const float2*)(ap + 20480);
        buf[0][j][2] = *(const float2*)(ap + 8);
        buf[0][j][3] = *(const float2*)(ap + 20488);
    }
    {
        #pragma unroll
        for (int jj = 0; jj < CPIT; jj++) {
            int idx = tid + jj * 256;
            int v = idx < NB8;
            int n = idx >> 3, q = idx & 7;
            uint32_t d = (uint32_t)(n * 128 + ((q ^ (n & 7)) << 4));
            cp16(su + d, BhT + n * 512 + q * 8, v);
        }
        asm volatile("cp.async.commit_group;" ::: "memory");
    }

    #pragma unroll 1
    for (int kc = 0; kc < 8; kc++) {
        const int s = kc & 1;

        // B(kc) ready; publish stage s
        asm volatile("cp.async.wait_group 0;" ::: "memory");
        __syncthreads();
        // issue B(kc+1) into stage s^1 (all warps are past reads of s^1)
        if (kc < 7) {
            const uint32_t bdst = su + (s ^ 1) * BB;
            const __half* bhs = BhT + (kc + 1) * 64;
            #pragma unroll
            for (int jj = 0; jj < CPIT; jj++) {
                int idx = tid + jj * 256;
                int v = idx < NB8;
                int n = idx >> 3, q = idx & 7;
                uint32_t d = (uint32_t)(n * 128 + ((q ^ (n & 7)) << 4));
                cp16(bdst + d, bhs + n * 512 + q * 8, v);
            }
            asm volatile("cp.async.commit_group;" ::: "memory");
        }

        const uint32_t bBase = su + s * BB;
        #pragma unroll
        for (int j = 0; j < 4; j++) {
            // convert current A fragment from reg buffer
            uint32_t ah[4];
            ah[0] = f16x2_rn(buf[s][j][0].x, buf[s][j][0].y);
            ah[1] = f16x2_rn(buf[s][j][1].x, buf[s][j][1].y);
            ah[2] = f16x2_rn(buf[s][j][2].x, buf[s][j][2].y);
            ah[3] = f16x2_rn(buf[s][j][3].x, buf[s][j][3].y);
            // staggered prefetch: chunk kc+1, fragment j (distance = 4 j-steps)
            if (kc < 7) {
                const float* ap = aw + (kc + 1) * 64 + j * 16;
                buf[s ^ 1][j][0] = *(const float2*)(ap);
                buf[s ^ 1][j][1] = *(const float2*)(ap + 20480);
                buf[s ^ 1][j][2] = *(const float2*)(ap + 8);
                buf[s ^ 1][j][3] = *(const float2*)(ap + 20488);
            }
            // B fragments + MMAs
            uint32_t bu = (uint32_t)(((2 * j + kuB) ^ sw) << 4);
            #pragma unroll
            for (int p = 0; p < PAIRS; p++) {
                uint32_t boff = (uint32_t)((16 * p + rBo) * 128) + bu;
                uint32_t bh[4];
                ldsm_x4(bh, bBase + boff);
                mma_f16(acc[2 * p],     ah, bh);
                mma_f16(acc[2 * p + 1], ah, bh + 2);
            }
            if (ODD) {
                uint32_t boff = (uint32_t)((16 * PAIRS + (lane & 7)) * 128) + bu;
                uint32_t bh[2];
                ldsm_x2(bh, bBase + boff);
                mma_f16(acc[NT - 1], ah, bh);
            }
        }
    }

    // ---- epilogue: bias + scatter ----
    const int g   = lane >> 2;
    const int tig = lane & 3;

    int   coff[NT][2];
    float cb[NT][2];
    #pragma unroll
    for (int t = 0; t < NT; t++) {
        #pragma unroll
        for (int h = 0; h < 2; h++) {
            int o = CO + 8 * t + 2 * tig + h;
            if (o < NREAL) {
                int p   = o / (GS * 3);
                int rem = o - p * (GS * 3);
                int joff = (GS == 5) ? ((rem < 3) ? rem : rem + 18) : (jb3 + rem);
                coff[t][h] = p * 51 + joff;
                cb[t][h]   = bias[o];
            } else {
                coff[t][h] = -1;
                cb[t][h]   = 0.f;
            }
        }
    }

    #pragma unroll
    for (int half = 0; half < 2; half++) {
        int m  = m0 + 16 * wid + g + 8 * half;
        int b  = m / 27;
        int tp = m - b * 27;
        size_t obase = (size_t)b * 12393 + (size_t)tp * 459;
        #pragma unroll
        for (int t = 0; t < NT; t++) {
            float v0 = acc[t][2 * half];
            float v1 = acc[t][2 * half + 1];
            if (coff[t][0] >= 0) out[obase + coff[t][0]] = v0 + cb[t][0];
            if (coff[t][1] >= 0) out[obase + coff[t][1]] = v1 + cb[t][1];
        }
    }
}

// One fused kernel. blockIdx.x = variant: 0..3 -> groups 0,1,3,4 (NPAD=88);
// 4,5 -> group 2 halves (NPAD=72). blockIdx.y = m-block (same token rows
// across all 6 variants -> L2 reuse).
__global__ void __launch_bounds__(256, 2) dec_all(
    const float* __restrict__ tokens,
    const float* __restrict__ b0, const float* __restrict__ b1,
    const float* __restrict__ b2, const float* __restrict__ b3,
    const float* __restrict__ b4,
    float* __restrict__ out)
{
    int y = blockIdx.x;
    if (y < 4) {
        int rowbase, gidx, jb3;
        const float* bias;
        switch (y) {
            case 0:  rowbase = 0;   gidx = 0; jb3 = 3;  bias = b0; break;
            case 1:  rowbase = 88;  gidx = 1; jb3 = 12; bias = b1; break;
            case 2:  rowbase = 320; gidx = 3; jb3 = 33; bias = b3; break;
            default: rowbase = 408; gidx = 4; jb3 = 42; bias = b4; break;
        }
        decode_core<88, 3, 0>(tokens, g_Bh + rowbase * 512, bias, out, gidx, jb3);
    } else if (y == 4) {
        decode_core<72, 5, 0>(tokens, g_Bh + 176 * 512, b2, out, 2, 0);
    } else {
        decode_core<72, 5, 72>(tokens, g_Bh + 248 * 512, b2, out, 2, 0);
    }
}

extern "C" void kernel_launch(void* const* d_in, const int* in_sizes, int n_in,
                              void* d_out, int out_size) {
    const float* tokens = (const float*)d_in[0];
    const float* W[5];
    const float* B[5];
    for (int i = 0; i < 5; i++) {
        W[i] = (const float*)d_in[1 + 2 * i];
        B[i] = (const float*)d_in[2 + 2 * i];
    }
    float* out = (float*)d_out;

    // dyn smem: 2 B stages of 88*128 = 22528 bytes max
    const int smem_sz = 2 * 88 * 128;

    prep_B<<<(496 * 128 + 255) / 256, 256>>>(W[0], W[1], W[2], W[3], W[4]);
    dec_all<<<dim3(6, 216), 256, smem_sz>>>(tokens, B[0], B[1], B[2], B[3], B[4], out);
}

// round 8
// speedup vs baseline: 1.7610x; 1.7610x over previous
#include <cuda_runtime.h>
#include <cuda_fp16.h>
#include <stdint.h>

// HybridMixSTEDecoder: 5 disjoint-group GEMMs (27648x512 @ 512xN_i) + bias,
// scattered into out[b, tp*9+p, joint, c]. Groups disjoint -> count/div identity.
//
// Single-pass fp16 mma.sync (A, B RN-rounded fp16, fp32 accum; rel_err ~3e-4).
// A fragments loaded direct from gmem as float4 per lane, using a per-16k-block
// K-PERMUTATION baked into B (prep_B) so the float4 maps exactly onto the mma
// A-fragment: eff(o) = 2*(o>>2) + (o&1) + 8*((o>>1)&1).
// Full-chunk A register buffer ra[8] (compile-time indices only -> no spills).
// B double-buffered in smem via cp.async. Grid (variant, m-block) for L2 reuse.

// Padded group rows: g0..g4 = 88,88,144,88,88 -> 496 rows of 512 fp16.
static __device__ __align__(16) __half g_Bh[496 * 512];

// ---------------- helpers ----------------
static __device__ __forceinline__ uint32_t s2u(const void* p) {
    uint32_t a;
    asm("{ .reg .u64 t; cvta.to.shared.u64 t, %1; cvt.u32.u64 %0, t; }"
        : "=r"(a) : "l"(p));
    return a;
}
static __device__ __forceinline__ uint32_t f16x2_rn(float lo, float hi) {
    uint32_t r; asm("cvt.rn.f16x2.f32 %0, %1, %2;" : "=r"(r) : "f"(hi), "f"(lo));
    return r;  // low half = lo, high half = hi
}
static __device__ __forceinline__ void ldsm_x4(uint32_t* r, uint32_t addr) {
    asm volatile("ldmatrix.sync.aligned.m8n8.x4.shared.b16 {%0,%1,%2,%3}, [%4];"
        : "=r"(r[0]), "=r"(r[1]), "=r"(r[2]), "=r"(r[3]) : "r"(addr));
}
static __device__ __forceinline__ void ldsm_x2(uint32_t* r, uint32_t addr) {
    asm volatile("ldmatrix.sync.aligned.m8n8.x2.shared.b16 {%0,%1}, [%2];"
        : "=r"(r[0]), "=r"(r[1]) : "r"(addr));
}
static __device__ __forceinline__ void mma_f16(float* d, const uint32_t* a,
                                               const uint32_t* b) {
    asm volatile(
        "mma.sync.aligned.m16n8k16.row.col.f32.f16.f16.f32 "
        "{%0,%1,%2,%3}, {%4,%5,%6,%7}, {%8,%9}, {%0,%1,%2,%3};"
        : "+f"(d[0]), "+f"(d[1]), "+f"(d[2]), "+f"(d[3])
        : "r"(a[0]), "r"(a[1]), "r"(a[2]), "r"(a[3]), "r"(b[0]), "r"(b[1]));
}
static __device__ __forceinline__ void cp16(uint32_t dst, const void* src, int pred) {
    asm volatile(
        "{\n\t.reg .pred p;\n\tsetp.ne.b32 p, %0, 0;\n\t"
        "@p cp.async.cg.shared.global [%1], [%2], 16;\n\t}"
        :: "r"(pred), "r"(dst), "l"(src));
}

// ---------------- prep: W (f32) -> fp16, [n][512] with per-16k permute ------
// Thread handles 4 consecutive k (o = k&15 in {0,4,8,12}, t = o>>2):
//   halves (k,k+1)   -> eff positions (2t, 2t+1)
//   halves (k+2,k+3) -> eff positions (2t+8, 2t+9)
__global__ void __launch_bounds__(256) prep_B(
    const float* __restrict__ W0, const float* __restrict__ W1,
    const float* __restrict__ W2, const float* __restrict__ W3,
    const float* __restrict__ W4)
{
    int idx = blockIdx.x * 256 + threadIdx.x;   // one thread per (grow, k4)
    if (idx >= 496 * 128) return;
    int grow = idx >> 7;
    int k = (idx & 127) << 2;
    int g, n;
    if      (grow <  88) { g = 0; n = grow;       }
    else if (grow < 176) { g = 1; n = grow -  88; }
    else if (grow < 320) { g = 2; n = grow - 176; }
    else if (grow < 408) { g = 3; n = grow - 320; }
    else                 { g = 4; n = grow - 408; }
    const float* Wg = (g == 0) ? W0 : (g == 1) ? W1 : (g == 2) ? W2
                    : (g == 3) ? W3 : W4;
    int Ng = (g == 2) ? 135 : 81;

    float4 v = make_float4(0.f, 0.f, 0.f, 0.f);
    if (n < Ng) v = *(const float4*)(Wg + n * 512 + k);

    uint32_t h01 = f16x2_rn(v.x, v.y);
    uint32_t h23 = f16x2_rn(v.z, v.w);
    uint32_t* dst = (uint32_t*)g_Bh + grow * 256 + ((k & ~15) >> 1) + ((k >> 2) & 3);
    dst[0] = h01;   // eff (2t, 2t+1)
    dst[4] = h23;   // eff (2t+8, 2t+9)
}

// ---------------- fused core ----------------
// Smem: two B stages of NPAD*128 bytes. 128B rows, XOR swizzle on 16B units.
template<int NPAD, int GS, int CO>
static __device__ __forceinline__ void decode_core(
    const float* __restrict__ tokens,
    const __half* __restrict__ BhT,
    const float* __restrict__ bias,
    float* __restrict__ out,
    int gidx, int jb3)
{
    constexpr int NT    = NPAD / 8;
    constexpr int PAIRS = NT / 2;
    constexpr int ODD   = NT & 1;
    constexpr int NREAL = (GS == 5) ? 135 : 81;
    constexpr int BB    = NPAD * 128;          // B tile bytes (one stage)
    constexpr int NB8   = NPAD * 8;            // cp.async 16B ops
    constexpr int CPIT  = (NB8 + 255) / 256;

    extern __shared__ char smem[];
    const uint32_t su = s2u(smem);

    const int tid  = threadIdx.x;
    const int wid  = tid >> 5;
    const int lane = tid & 31;

    const int m0 = blockIdx.y * 128;

    // A direct-load geometry with the k-permute: lane (r = lane>>2, tig = lane&3)
    // loads float4 at (row r, k = 16j + 4*tig) and (row r+8, same k).
    const float* aw = tokens
        + (size_t)(m0 + 16 * wid + (lane >> 2)) * 2560
        + gidx * 512 + (lane & 3) * 4;

    // ldmatrix B geometry
    const int rBo = (lane & 7) + ((lane & 16) ? 8 : 0);
    const int kuB = (lane >> 3) & 1;
    const int sw  = lane & 7;

    float acc[NT][4];
    #pragma unroll
    for (int t = 0; t < NT; t++)
        #pragma unroll
        for (int q = 0; q < 4; q++) acc[t][q] = 0.f;

    // Full-chunk A register buffer (compile-time indices only).
    float4 ra[8];
    #pragma unroll
    for (int j = 0; j < 4; j++) {
        ra[2 * j]     = *(const float4*)(aw + j * 16);
        ra[2 * j + 1] = *(const float4*)(aw + j * 16 + 20480);
    }
    // B(0) cp.async
    {
        #pragma unroll
        for (int jj = 0; jj < CPIT; jj++) {
            int idx = tid + jj * 256;
            int v = idx < NB8;
            int n = idx >> 3, q = idx & 7;
            uint32_t d = (uint32_t)(n * 128 + ((q ^ (n & 7)) << 4));
            cp16(su + d, BhT + n * 512 + q * 8, v);
        }
        asm volatile("cp.async.commit_group;" ::: "memory");
    }

    #pragma unroll 1
    for (int kc = 0; kc < 8; kc++) {
        const int s = kc & 1;

        // B(kc) ready; publish stage s
        asm volatile("cp.async.wait_group 0;" ::: "memory");
        __syncthreads();
        // issue B(kc+1) into stage s^1 (all warps are past reads of s^1)
        if (kc < 7) {
            const uint32_t bdst = su + (s ^ 1) * BB;
            const __half* bhs = BhT + (kc + 1) * 64;
            #pragma unroll
            for (int jj = 0; jj < CPIT; jj++) {
                int idx = tid + jj * 256;
                int v = idx < NB8;
                int n = idx >> 3, q = idx & 7;
                uint32_t d = (uint32_t)(n * 128 + ((q ^ (n & 7)) << 4));
                cp16(bdst + d, bhs + n * 512 + q * 8, v);
            }
            asm volatile("cp.async.commit_group;" ::: "memory");
        }

        const uint32_t bBase = su + s * BB;
        #pragma unroll
        for (int j = 0; j < 4; j++) {
            // convert current A fragment (permuted layout: float4 -> a0,a2)
            uint32_t ah[4];
            ah[0] = f16x2_rn(ra[2 * j].x,     ra[2 * j].y);
            ah[2] = f16x2_rn(ra[2 * j].z,     ra[2 * j].w);
            ah[1] = f16x2_rn(ra[2 * j + 1].x, ra[2 * j + 1].y);
            ah[3] = f16x2_rn(ra[2 * j + 1].z, ra[2 * j + 1].w);
            // refill this slot from chunk kc+1 (lookahead ~4 j-steps)
            if (kc < 7) {
                const float* ap = aw + (kc + 1) * 64 + j * 16;
                ra[2 * j]     = *(const float4*)(ap);
                ra[2 * j + 1] = *(const float4*)(ap + 20480);
            }
            // B fragments + MMAs
            uint32_t bu = (uint32_t)(((2 * j + kuB) ^ sw) << 4);
            #pragma unroll
            for (int p = 0; p < PAIRS; p++) {
                uint32_t boff = (uint32_t)((16 * p + rBo) * 128) + bu;
                uint32_t bh[4];
                ldsm_x4(bh, bBase + boff);
                mma_f16(acc[2 * p],     ah, bh);
                mma_f16(acc[2 * p + 1], ah, bh + 2);
            }
            if (ODD) {
                uint32_t boff = (uint32_t)((16 * PAIRS + (lane & 7)) * 128) + bu;
                uint32_t bh[2];
                ldsm_x2(bh, bBase + boff);
                mma_f16(acc[NT - 1], ah, bh);
            }
        }
    }

    // ---- epilogue: bias + scatter ----
    const int g   = lane >> 2;
    const int tig = lane & 3;

    int   coff[NT][2];
    float cb[NT][2];
    #pragma unroll
    for (int t = 0; t < NT; t++) {
        #pragma unroll
        for (int h = 0; h < 2; h++) {
            int o = CO + 8 * t + 2 * tig + h;
            if (o < NREAL) {
                int p   = o / (GS * 3);
                int rem = o - p * (GS * 3);
                int joff = (GS == 5) ? ((rem < 3) ? rem : rem + 18) : (jb3 + rem);
                coff[t][h] = p * 51 + joff;
                cb[t][h]   = bias[o];
            } else {
                coff[t][h] = -1;
                cb[t][h]   = 0.f;
            }
        }
    }

    #pragma unroll
    for (int half = 0; half < 2; half++) {
        int m  = m0 + 16 * wid + g + 8 * half;
        int b  = m / 27;
        int tp = m - b * 27;
        size_t obase = (size_t)b * 12393 + (size_t)tp * 459;
        #pragma unroll
        for (int t = 0; t < NT; t++) {
            float v0 = acc[t][2 * half];
            float v1 = acc[t][2 * half + 1];
            if (coff[t][0] >= 0) out[obase + coff[t][0]] = v0 + cb[t][0];
            if (coff[t][1] >= 0) out[obase + coff[t][1]] = v1 + cb[t][1];
        }
    }
}

// One fused kernel. blockIdx.x = variant: 0..3 -> groups 0,1,3,4 (NPAD=88);
// 4,5 -> group 2 halves (NPAD=72). blockIdx.y = m-block (same token rows
// across all 6 variants -> L2 reuse for g2 double-read + output merging).
__global__ void __launch_bounds__(256, 2) dec_all(
    const float* __restrict__ tokens,
    const float* __restrict__ b0, const float* __restrict__ b1,
    const float* __restrict__ b2, const float* __restrict__ b3,
    const float* __restrict__ b4,
    float* __restrict__ out)
{
    int y = blockIdx.x;
    if (y < 4) {
        int rowbase, gidx, jb3;
        const float* bias;
        switch (y) {
            case 0:  rowbase = 0;   gidx = 0; jb3 = 3;  bias = b0; break;
            case 1:  rowbase = 88;  gidx = 1; jb3 = 12; bias = b1; break;
            case 2:  rowbase = 320; gidx = 3; jb3 = 33; bias = b3; break;
            default: rowbase = 408; gidx = 4; jb3 = 42; bias = b4; break;
        }
        decode_core<88, 3, 0>(tokens, g_Bh + rowbase * 512, bias, out, gidx, jb3);
    } else if (y == 4) {
        decode_core<72, 5, 0>(tokens, g_Bh + 176 * 512, b2, out, 2, 0);
    } else {
        decode_core<72, 5, 72>(tokens, g_Bh + 248 * 512, b2, out, 2, 0);
    }
}

extern "C" void kernel_launch(void* const* d_in, const int* in_sizes, int n_in,
                              void* d_out, int out_size) {
    const float* tokens = (const float*)d_in[0];
    const float* W[5];
    const float* B[5];
    for (int i = 0; i < 5; i++) {
        W[i] = (const float*)d_in[1 + 2 * i];
        B[i] = (const float*)d_in[2 + 2 * i];
    }
    float* out = (float*)d_out;

    // dyn smem: 2 B stages of 88*128 = 22528 bytes max
    const int smem_sz = 2 * 88 * 128;

    prep_B<<<(496 * 128 + 255) / 256, 256>>>(W[0], W[1], W[2], W[3], W[4]);
    dec_all<<<dim3(6, 216), 256, smem_sz>>>(tokens, B[0], B[1], B[2], B[3], B[4], out);
}